// round 14
// baseline (speedup 1.0000x reference)
#include <cuda_runtime.h>

// Problem constants
#define BB 64      // batch
#define SS 256     // seq length
#define VV 2048    // ntokens
#define HH 512     // nhid
#define NSPLIT 8   // sequence splits for the gather
#define SP (SS / NSPLIT)   // positions per gather CTA = 32
#define MCTA2 128  // CTAs per fused-MLP half instance (single wave)

// Scratch (no allocations). Zero-initialized at module load.
// Each half's g_h1pre slice is re-zeroed by its own k_mlp phase B.
__device__ float g_h1pre[BB * HH];          // gather accumulator (pre bias/relu)
__device__ float g_h2part[8][BB][HH];       // GEMM1 K-split partials (no atomics)
__device__ unsigned g_bar2[2];              // per-half generation barriers

// ---------------------------------------------------------------------------
// K1: gather partial-sum for 32 batches -> atomicAdd into g_h1pre.
// grid = (128, 8): x = 32 batches x 4 H-chunks, y = 8 seq-splits of 32.
// (Proven R4/R11 inner structure — sits at the ~2.85 TB/s pattern ceiling.)
// y==0 slice also seeds this half's out rows = b3.
// ---------------------------------------------------------------------------
__global__ void k_gather(const int* __restrict__ x32,
                         const float* __restrict__ W1,
                         const float* __restrict__ b3,
                         float* __restrict__ out,
                         const int mhalf) {            // 0 or 32
    const int t = threadIdx.x;

    if (blockIdx.y == 0) {
        const int gid = blockIdx.x * 128 + t;          // 0..16383
        if (gid < 32 * SS) out[mhalf * SS + gid] = b3[gid & (SS - 1)];
    }

    __shared__ int s_is64;
    if (t == 0) s_is64 = 1;
    __syncthreads();
    if (x32[2 * t + 1] != 0) s_is64 = 0;   // racy same-value store: fine
    __syncthreads();
    const int is64 = s_is64;

    const int b  = mhalf + (blockIdx.x >> 2);          // batch
    const int h  = ((blockIdx.x & 3) << 7) | t;        // 0..511
    const int p0 = blockIdx.y * SP;                    // first position

    __shared__ unsigned rb[SP];
    if (t < SP) {
        unsigned tok;
        if (is64) tok = (unsigned)((const long long*)x32)[b * SS + p0 + t];
        else      tok = (unsigned)x32[b * SS + p0 + t];
        rb[t] = (tok + (unsigned)(p0 + t) * VV) << 9;   // * HH
    }
    __syncthreads();

    float a0 = 0.f, a1 = 0.f, a2 = 0.f, a3 = 0.f;
    #pragma unroll
    for (int p = 0; p < SP; p += 4) {
        a0 += W1[rb[p + 0] + h];
        a1 += W1[rb[p + 1] + h];
        a2 += W1[rb[p + 2] + h];
        a3 += W1[rb[p + 3] + h];
    }
    atomicAdd(&g_h1pre[b * HH + h], (a0 + a1) + (a2 + a3));
}

// ---------------------------------------------------------------------------
// K2: fused MLP for one 32-batch half. 128 CTAs x 128 threads (single wave).
// Phase A: g_h2part[kbs][mhalf..+32] = relu(h1pre+b1) @ W2   (STG, no atomics)
// barrier  (per-half generation counter)
// Phase B: out[mhalf..] += relu(sum_p h2part + b2) @ W3 (K-split, atomics);
//          also resets this half's g_h1pre slice.
// ---------------------------------------------------------------------------
__global__ void __launch_bounds__(128) k_mlp(
        const float* __restrict__ b1,
        const float* __restrict__ W2,
        const float* __restrict__ b2,
        const float* __restrict__ W3,
        float* __restrict__ out,
        const int half) {                    // 0 or 1
    const int t     = threadIdx.x;
    const int cta   = blockIdx.x;
    const int mhalf = half * 32;
    const int m2    = (t >> 3) * 2;          // 0..30
    const int n4    = (t & 7) * 4;           // 0..28

    __shared__ float As[32][33];
    __shared__ __align__(16) float Bs[32][32];

    // ---- Phase A: GEMM1 partial (nb = 32-col tile, kbs = 64-wide K-split) --
    {
        const int nb  = (cta & 15) * 32;
        const int kbs = cta >> 4;            // 0..7
        const int kb  = kbs * 64;
        float acc[2][4] = {};

        for (int kk = 0; kk < 64; kk += 32) {
            __syncthreads();
            #pragma unroll
            for (int i = 0; i < 2; i++) {           // As: 32x32, float4 loads
                int idx = i * 128 + t;
                int mm = idx >> 3, k4 = (idx & 7) * 4;
                int kg = kb + kk + k4;
                float4 v  = *(const float4*)&g_h1pre[(mhalf + mm) * HH + kg];
                float4 bb = *(const float4*)&b1[kg];
                As[mm][k4 + 0] = fmaxf(v.x + bb.x, 0.f);
                As[mm][k4 + 1] = fmaxf(v.y + bb.y, 0.f);
                As[mm][k4 + 2] = fmaxf(v.z + bb.z, 0.f);
                As[mm][k4 + 3] = fmaxf(v.w + bb.w, 0.f);
            }
            #pragma unroll
            for (int i = 0; i < 2; i++) {           // Bs: 32x32, float4 loads
                int idx = i * 128 + t;
                int k = idx >> 3, nn4 = (idx & 7) * 4;
                *(float4*)&Bs[k][nn4] =
                    *(const float4*)&W2[(kb + kk + k) * HH + nb + nn4];
            }
            __syncthreads();

            #pragma unroll
            for (int k = 0; k < 32; k++) {
                float4 b4 = *(const float4*)&Bs[k][n4];
                float a0 = As[m2 + 0][k];
                float a1 = As[m2 + 1][k];
                acc[0][0] += a0 * b4.x; acc[0][1] += a0 * b4.y;
                acc[0][2] += a0 * b4.z; acc[0][3] += a0 * b4.w;
                acc[1][0] += a1 * b4.x; acc[1][1] += a1 * b4.y;
                acc[1][2] += a1 * b4.z; acc[1][3] += a1 * b4.w;
            }
        }
        #pragma unroll
        for (int i = 0; i < 2; i++)                 // STG.128, no atomics
            *(float4*)&g_h2part[kbs][mhalf + m2 + i][nb + n4] =
                make_float4(acc[i][0], acc[i][1], acc[i][2], acc[i][3]);
    }

    // ---- Per-half grid barrier (generation-counting, replay-safe) -------
    __syncthreads();
    if (t == 0) {
        __threadfence();
        unsigned v = atomicAdd(&g_bar2[half], 1u);
        unsigned tgt = (v / MCTA2 + 1u) * MCTA2;
        unsigned cur;
        do {
            asm volatile("ld.acquire.gpu.global.u32 %0, [%1];"
                         : "=r"(cur) : "l"(&g_bar2[half]) : "memory");
            if (cur < tgt) __nanosleep(32);
        } while (cur < tgt);
        __threadfence();
    }
    __syncthreads();

    // ---- Phase B: reset this half's h1pre + GEMM2 -----------------------
    {   // 128 CTAs x 128 thr = 16384 = exactly this half's slice.
        g_h1pre[half * 16384 + cta * 128 + t] = 0.0f;
    }
    {
        const int nb = (cta & 7) * 32;
        const int kb = (cta >> 3) * 32;              // 16 k-splits of 32
        float acc[2][4] = {};

        __syncthreads();
        #pragma unroll
        for (int i = 0; i < 2; i++) {               // As = relu(sum partials + b2)
            int idx = i * 128 + t;
            int mm = idx >> 3, k4 = (idx & 7) * 4;
            int kg = kb + k4;
            float4 s = *(const float4*)&b2[kg];
            #pragma unroll
            for (int p = 0; p < 8; p++) {
                float4 v = *(const float4*)&g_h2part[p][mhalf + mm][kg];
                s.x += v.x; s.y += v.y; s.z += v.z; s.w += v.w;
            }
            As[mm][k4 + 0] = fmaxf(s.x, 0.f);
            As[mm][k4 + 1] = fmaxf(s.y, 0.f);
            As[mm][k4 + 2] = fmaxf(s.z, 0.f);
            As[mm][k4 + 3] = fmaxf(s.w, 0.f);
        }
        #pragma unroll
        for (int i = 0; i < 2; i++) {               // Bs: 32x32 of W3
            int idx = i * 128 + t;
            int k = idx >> 3, nn4 = (idx & 7) * 4;
            *(float4*)&Bs[k][nn4] =
                *(const float4*)&W3[(kb + k) * SS + nb + nn4];
        }
        __syncthreads();

        #pragma unroll
        for (int k = 0; k < 32; k++) {
            float4 b4 = *(const float4*)&Bs[k][n4];
            float a0 = As[m2 + 0][k];
            float a1 = As[m2 + 1][k];
            acc[0][0] += a0 * b4.x; acc[0][1] += a0 * b4.y;
            acc[0][2] += a0 * b4.z; acc[0][3] += a0 * b4.w;
            acc[1][0] += a1 * b4.x; acc[1][1] += a1 * b4.y;
            acc[1][2] += a1 * b4.z; acc[1][3] += a1 * b4.w;
        }

        #pragma unroll
        for (int i = 0; i < 2; i++)
            #pragma unroll
            for (int j = 0; j < 4; j++)
                atomicAdd(&out[(mhalf + m2 + i) * SS + nb + n4 + j], acc[i][j]);
    }
}

// ---------------------------------------------------------------------------
// Host-side stream/event resources: created once at module load (host
// resources only; the GPU work enqueued per call is identical every call).
// ---------------------------------------------------------------------------
static cudaStream_t g_s2;
static cudaEvent_t  g_evA, g_evB;
namespace {
struct StreamInit {
    StreamInit() {
        cudaStreamCreateWithFlags(&g_s2, cudaStreamNonBlocking);
        cudaEventCreateWithFlags(&g_evA, cudaEventDisableTiming);
        cudaEventCreateWithFlags(&g_evB, cudaEventDisableTiming);
    }
};
static StreamInit g_si;
}

// ---------------------------------------------------------------------------
// Pipeline:
//   default: gatherA -> mlpA -------------------> mlpB
//   s2:            \-evA-> gatherB ----evB----------^
// gatherB (bandwidth-bound) overlaps mlpA (compute-bound).
// ---------------------------------------------------------------------------
extern "C" void kernel_launch(void* const* d_in, const int* in_sizes, int n_in,
                              void* d_out, int out_size) {
    const int*   x  = (const int*)d_in[0];   // int32 or int64, detected on device
    const float* W1 = (const float*)d_in[1];
    const float* b1 = (const float*)d_in[2];
    const float* W2 = (const float*)d_in[3];
    const float* b2 = (const float*)d_in[4];
    const float* W3 = (const float*)d_in[5];
    const float* b3 = (const float*)d_in[6];
    float* out = (float*)d_out;

    // Half A gather on the default stream.
    k_gather<<<dim3(128, NSPLIT), 128>>>(x, W1, b3, out, 0);
    cudaEventRecord(g_evA, 0);

    // Half B gather on s2, after gather A (they would only share bandwidth).
    cudaStreamWaitEvent(g_s2, g_evA, 0);
    k_gather<<<dim3(128, NSPLIT), 128, 0, g_s2>>>(x, W1, b3, out, 32);
    cudaEventRecord(g_evB, g_s2);

    // Half A MLP runs concurrently with half B's gather.
    k_mlp<<<MCTA2, 128>>>(b1, W2, b2, W3, out, 0);

    // Half B MLP after both mlpA (in-stream) and gatherB (event).
    cudaStreamWaitEvent(0, g_evB, 0);
    k_mlp<<<MCTA2, 128>>>(b1, W2, b2, W3, out, 1);
}

// round 15
// speedup vs baseline: 1.4087x; 1.4087x over previous
#include <cuda_runtime.h>

// Problem constants
#define BB 64      // batch
#define SS 256     // seq length
#define VV 2048    // ntokens
#define HH 512     // nhid

// Scratch (no allocations). Zero-initialized at module load.
// Each half's g_h1pre slice is re-zeroed by that half's MLP phase B.
__device__ float g_h1pre[BB * HH];          // gather accumulator (pre bias/relu)
__device__ float g_h2part[8][BB][HH];       // GEMM1 K-split partials (no atomics)
__device__ unsigned g_done[2];              // gather arrivals per half (monotonic)
__device__ unsigned g_mbar[2];              // 128-CTA MLP barrier per half (monotonic)

// ---------------------------------------------------------------------------
// ONE kernel. grid = 2048 CTAs x 128 threads.
//   bid 0..1023    : half A (batches 0..31)   gather slices
//   bid 1024..2047 : half B (batches 32..63)  gather slices
// Gather slice (R4 structure, proven at the ~2.85TB/s pattern ceiling):
//   xi = 32 batches x 4 h-chunks, yi = 8 position-splits of 32.
// After its gather, each CTA takes an arrival ticket for its half.
//   ticket < 896  -> exit (frees the SM).
//   ticket >= 896 -> wait for all 1024 arrivals of this half, then run the
//                    half's MLP as mlp-CTA (ticket-896) of 128:
//                    GEMM1 (stores) -> 128-CTA barrier -> GEMM2 (+h1pre reset).
// Half A's MLP overlaps half B's still-running gather.  All counters are
// monotonic generation counters -> graph-replay-safe with no resets.
// ---------------------------------------------------------------------------
__global__ void __launch_bounds__(128) k_all(
        const int* __restrict__ x32,
        const float* __restrict__ W1,
        const float* __restrict__ b1,
        const float* __restrict__ W2,
        const float* __restrict__ b2,
        const float* __restrict__ W3,
        const float* __restrict__ b3,
        float* __restrict__ out) {
    const int t     = threadIdx.x;
    const int bid   = blockIdx.x;
    const int half  = bid >> 10;
    const int local = bid & 1023;
    const int xi    = local & 127;        // 32 batches x 4 h-chunks
    const int yi    = local >> 7;         // 8 position splits
    const int mhalf = half * 32;

    __shared__ unsigned rb[32];
    __shared__ int s_is64;
    __shared__ int s_go;                  // mlp id or -1
    __shared__ float As[32][33];
    __shared__ __align__(16) float Bs[32][32];

    // ---- Gather ---------------------------------------------------------
    // Seed this half's out rows = b3 (yi==0 slice; out poisoned pre-timing).
    if (yi == 0) {
        const int gid = xi * 128 + t;                 // 0..16383
        if (gid < 32 * SS) out[mhalf * SS + gid] = b3[gid & (SS - 1)];
    }

    // Index dtype detect: int64 -> odd 32-bit words of first 128 elems are 0.
    if (t == 0) s_is64 = 1;
    __syncthreads();
    if (x32[2 * t + 1] != 0) s_is64 = 0;              // racy same-value: fine
    __syncthreads();

    const int b  = mhalf + (xi >> 2);                 // batch
    const int h  = ((xi & 3) << 7) | t;               // 0..511
    const int p0 = yi * 32;                           // first position

    if (t < 32) {
        unsigned tok;
        if (s_is64) tok = (unsigned)((const long long*)x32)[b * SS + p0 + t];
        else        tok = (unsigned)x32[b * SS + p0 + t];
        rb[t] = (tok + (unsigned)(p0 + t) * VV) << 9;   // * HH
    }
    __syncthreads();

    float a0 = 0.f, a1 = 0.f, a2 = 0.f, a3 = 0.f;
    #pragma unroll
    for (int p = 0; p < 32; p += 4) {
        a0 += W1[rb[p + 0] + h];
        a1 += W1[rb[p + 1] + h];
        a2 += W1[rb[p + 2] + h];
        a3 += W1[rb[p + 3] + h];
    }
    atomicAdd(&g_h1pre[b * HH + h], (a0 + a1) + (a2 + a3));

    // ---- Arrival ticket -------------------------------------------------
    __threadfence();            // make my atomics globally visible
    __syncthreads();            // all threads' fences done before arrival
    if (t == 0) {
        unsigned v = atomicAdd(&g_done[half], 1u);
        unsigned ticket = v & 1023u;                  // 1024 arrivals/half/call
        if (ticket >= 896u) {
            // Last 128 arrivals: wait for the whole half, then do MLP.
            unsigned tgt = (v / 1024u + 1u) * 1024u;
            unsigned cur;
            do {
                asm volatile("ld.acquire.gpu.global.u32 %0, [%1];"
                             : "=r"(cur) : "l"(&g_done[half]) : "memory");
                if (cur < tgt) __nanosleep(32);
            } while (cur < tgt);
            __threadfence();
            s_go = (int)(ticket - 896u);              // 0..127
        } else {
            s_go = -1;
        }
    }
    __syncthreads();
    const int cta = s_go;
    if (cta < 0) return;                              // free the SM

    // ---- Phase A: GEMM1 partial for this half ---------------------------
    // g_h2part[kbs][mhalf..+32] = relu(h1pre+b1) @ W2   (STG.128, no atomics)
    const int m2 = (t >> 3) * 2;         // 0..30
    const int n4 = (t & 7) * 4;          // 0..28
    {
        const int nb  = (cta & 15) * 32;
        const int kbs = cta >> 4;        // 0..7
        const int kb  = kbs * 64;
        float acc[2][4] = {};

        for (int kk = 0; kk < 64; kk += 32) {
            __syncthreads();
            #pragma unroll
            for (int i = 0; i < 2; i++) {            // As: 32x32, float4 loads
                int idx = i * 128 + t;
                int mm = idx >> 3, k4 = (idx & 7) * 4;
                int kg = kb + kk + k4;
                float4 v  = *(const float4*)&g_h1pre[(mhalf + mm) * HH + kg];
                float4 bb = *(const float4*)&b1[kg];
                As[mm][k4 + 0] = fmaxf(v.x + bb.x, 0.f);
                As[mm][k4 + 1] = fmaxf(v.y + bb.y, 0.f);
                As[mm][k4 + 2] = fmaxf(v.z + bb.z, 0.f);
                As[mm][k4 + 3] = fmaxf(v.w + bb.w, 0.f);
            }
            #pragma unroll
            for (int i = 0; i < 2; i++) {            // Bs: 32x32, float4 loads
                int idx = i * 128 + t;
                int k = idx >> 3, nn4 = (idx & 7) * 4;
                *(float4*)&Bs[k][nn4] =
                    *(const float4*)&W2[(kb + kk + k) * HH + nb + nn4];
            }
            __syncthreads();

            #pragma unroll
            for (int k = 0; k < 32; k++) {
                float4 b4 = *(const float4*)&Bs[k][n4];
                float v0 = As[m2 + 0][k];
                float v1 = As[m2 + 1][k];
                acc[0][0] += v0 * b4.x; acc[0][1] += v0 * b4.y;
                acc[0][2] += v0 * b4.z; acc[0][3] += v0 * b4.w;
                acc[1][0] += v1 * b4.x; acc[1][1] += v1 * b4.y;
                acc[1][2] += v1 * b4.z; acc[1][3] += v1 * b4.w;
            }
        }
        #pragma unroll
        for (int i = 0; i < 2; i++)                  // STG.128, no atomics
            *(float4*)&g_h2part[kbs][mhalf + m2 + i][nb + n4] =
                make_float4(acc[i][0], acc[i][1], acc[i][2], acc[i][3]);
    }

    // ---- 128-CTA barrier for this half (generation, replay-safe) --------
    __syncthreads();
    if (t == 0) {
        __threadfence();
        unsigned v = atomicAdd(&g_mbar[half], 1u);
        unsigned tgt = (v / 128u + 1u) * 128u;
        unsigned cur;
        do {
            asm volatile("ld.acquire.gpu.global.u32 %0, [%1];"
                         : "=r"(cur) : "l"(&g_mbar[half]) : "memory");
            if (cur < tgt) __nanosleep(32);
        } while (cur < tgt);
        __threadfence();
    }
    __syncthreads();

    // ---- Phase B: GEMM2 for this half + h1pre reset ----------------------
    // Reset this half's h1pre slice (last reader was Phase A staging).
    g_h1pre[half * 16384 + cta * 128 + t] = 0.0f;
    {
        const int nb = (cta & 7) * 32;
        const int kb = (cta >> 3) * 32;              // 16 k-splits of 32
        float acc[2][4] = {};

        __syncthreads();
        #pragma unroll
        for (int i = 0; i < 2; i++) {               // As = relu(sum partials + b2)
            int idx = i * 128 + t;
            int mm = idx >> 3, k4 = (idx & 7) * 4;
            int kg = kb + k4;
            float4 s = *(const float4*)&b2[kg];
            #pragma unroll
            for (int p = 0; p < 8; p++) {
                float4 v = *(const float4*)&g_h2part[p][mhalf + mm][kg];
                s.x += v.x; s.y += v.y; s.z += v.z; s.w += v.w;
            }
            As[mm][k4 + 0] = fmaxf(s.x, 0.f);
            As[mm][k4 + 1] = fmaxf(s.y, 0.f);
            As[mm][k4 + 2] = fmaxf(s.z, 0.f);
            As[mm][k4 + 3] = fmaxf(s.w, 0.f);
        }
        #pragma unroll
        for (int i = 0; i < 2; i++) {               // Bs: 32x32 of W3
            int idx = i * 128 + t;
            int k = idx >> 3, nn4 = (idx & 7) * 4;
            *(float4*)&Bs[k][nn4] =
                *(const float4*)&W3[(kb + k) * SS + nb + nn4];
        }
        __syncthreads();

        #pragma unroll
        for (int k = 0; k < 32; k++) {
            float4 b4 = *(const float4*)&Bs[k][n4];
            float v0 = As[m2 + 0][k];
            float v1 = As[m2 + 1][k];
            acc[0][0] += v0 * b4.x; acc[0][1] += v0 * b4.y;
            acc[0][2] += v0 * b4.z; acc[0][3] += v0 * b4.w;
            acc[1][0] += v1 * b4.x; acc[1][1] += v1 * b4.y;
            acc[1][2] += v1 * b4.z; acc[1][3] += v1 * b4.w;
        }

        #pragma unroll
        for (int i = 0; i < 2; i++)
            #pragma unroll
            for (int j = 0; j < 4; j++)
                atomicAdd(&out[(mhalf + m2 + i) * SS + nb + n4 + j], acc[i][j]);
    }
}

// ---------------------------------------------------------------------------
extern "C" void kernel_launch(void* const* d_in, const int* in_sizes, int n_in,
                              void* d_out, int out_size) {
    const int*   x  = (const int*)d_in[0];   // int32 or int64, detected on device
    const float* W1 = (const float*)d_in[1];
    const float* b1 = (const float*)d_in[2];
    const float* W2 = (const float*)d_in[3];
    const float* b2 = (const float*)d_in[4];
    const float* W3 = (const float*)d_in[5];
    const float* b3 = (const float*)d_in[6];
    float* out = (float*)d_out;

    k_all<<<2048, 128>>>(x, W1, b1, W2, b2, W3, b3, out);
}

// round 16
// speedup vs baseline: 1.6814x; 1.1936x over previous
#include <cuda_runtime.h>

// Problem constants
#define BB 64      // batch
#define SS 256     // seq length
#define VV 2048    // ntokens
#define HH 512     // nhid
#define NSPLIT 16  // sequence splits for the gather (probe: 2x R11's CTA count)
#define SP (SS / NSPLIT)   // positions per gather CTA = 16

// Scratch (no allocations). Zero-initialized at module load.
// g_h1pre's ==0 invariant is restored by k_gemm2 each call.
__device__ float g_h1pre[BB * HH];          // gather accumulator (pre bias/relu)
__device__ float g_h2part[8][BB][HH];       // GEMM1 K-split partials (no atomics)

// ---------------------------------------------------------------------------
// K1: gather partial-sum -> atomicAdd into g_h1pre.
// grid = (256, 16): x = 64 batches x 4 H-chunks, y = 16 seq-splits of 16.
// block = 128 threads (one h column each). y==0 slice also seeds out = b3.
// Probe: 4096 CTAs (vs R4/R11's 2048) — tests whether gather BW scales with
// resident CTA count (R2->R4 doubled BW this way) or is pattern-ceiling-bound.
// Handles both int64 and int32 index layouts (runtime-detected).
// ---------------------------------------------------------------------------
__global__ void k_gather(const int* __restrict__ x32,
                         const float* __restrict__ W1,
                         const float* __restrict__ b3,
                         float* __restrict__ out) {
    const int t = threadIdx.x;

    if (blockIdx.y == 0) {
        const int gid = blockIdx.x * 128 + t;        // 0..32767
        if (gid < BB * SS) out[gid] = b3[gid & (SS - 1)];
    }

    __shared__ int s_is64;
    if (t == 0) s_is64 = 1;
    __syncthreads();
    if (x32[2 * t + 1] != 0) s_is64 = 0;   // racy same-value store: fine
    __syncthreads();
    const int is64 = s_is64;

    const int b  = blockIdx.x >> 2;                   // batch
    const int h  = ((blockIdx.x & 3) << 7) | t;       // 0..511
    const int p0 = blockIdx.y * SP;                   // first position

    __shared__ unsigned rb[SP];
    if (t < SP) {
        unsigned tok;
        if (is64) tok = (unsigned)((const long long*)x32)[b * SS + p0 + t];
        else      tok = (unsigned)x32[b * SS + p0 + t];
        rb[t] = (tok + (unsigned)(p0 + t) * VV) << 9;   // * HH
    }
    __syncthreads();

    float a0 = 0.f, a1 = 0.f, a2 = 0.f, a3 = 0.f;
    #pragma unroll
    for (int p = 0; p < SP; p += 4) {
        a0 += W1[rb[p + 0] + h];
        a1 += W1[rb[p + 1] + h];
        a2 += W1[rb[p + 2] + h];
        a3 += W1[rb[p + 3] + h];
    }
    atomicAdd(&g_h1pre[b * HH + h], (a0 + a1) + (a2 + a3));
}

// ---------------------------------------------------------------------------
// K2: GEMM1 partial: g_h2part[kbs] = relu(h1pre+b1)[:, kb..] @ W2[kb.., nb..]
// grid = (16 n-tiles of 32, 8 k-splits of 64), block = 128 threads.
// Pure STG.128 epilogue -> zero atomics.  float4 staging everywhere.
// ---------------------------------------------------------------------------
__global__ void __launch_bounds__(128) k_gemm1(
        const float* __restrict__ b1,
        const float* __restrict__ W2) {
    const int nb  = blockIdx.x * 32;
    const int kbs = blockIdx.y;          // 0..7
    const int kb  = kbs * 64;
    const int t   = threadIdx.x;
    const int m4  = (t >> 3) * 4;        // 0..60
    const int n4  = (t & 7) * 4;         // 0..28

    __shared__ float As[64][33];
    __shared__ __align__(16) float Bs[32][32];

    float acc[4][4] = {};

    for (int kk = 0; kk < 64; kk += 32) {
        __syncthreads();
        #pragma unroll
        for (int i = 0; i < 4; i++) {           // As: 64x32, float4 loads
            int idx = i * 128 + t;
            int mm = idx >> 3, k4 = (idx & 7) * 4;
            int kg = kb + kk + k4;
            float4 v  = *(const float4*)&g_h1pre[mm * HH + kg];
            float4 bb = *(const float4*)&b1[kg];
            As[mm][k4 + 0] = fmaxf(v.x + bb.x, 0.f);
            As[mm][k4 + 1] = fmaxf(v.y + bb.y, 0.f);
            As[mm][k4 + 2] = fmaxf(v.z + bb.z, 0.f);
            As[mm][k4 + 3] = fmaxf(v.w + bb.w, 0.f);
        }
        #pragma unroll
        for (int i = 0; i < 2; i++) {           // Bs: 32x32, float4 loads
            int idx = i * 128 + t;
            int k = idx >> 3, nn4 = (idx & 7) * 4;
            *(float4*)&Bs[k][nn4] =
                *(const float4*)&W2[(kb + kk + k) * HH + nb + nn4];
        }
        __syncthreads();

        #pragma unroll
        for (int k = 0; k < 32; k++) {
            float4 b4 = *(const float4*)&Bs[k][n4];
            float a0 = As[m4 + 0][k];
            float a1 = As[m4 + 1][k];
            float a2 = As[m4 + 2][k];
            float a3 = As[m4 + 3][k];
            acc[0][0] += a0 * b4.x; acc[0][1] += a0 * b4.y; acc[0][2] += a0 * b4.z; acc[0][3] += a0 * b4.w;
            acc[1][0] += a1 * b4.x; acc[1][1] += a1 * b4.y; acc[1][2] += a1 * b4.z; acc[1][3] += a1 * b4.w;
            acc[2][0] += a2 * b4.x; acc[2][1] += a2 * b4.y; acc[2][2] += a2 * b4.z; acc[2][3] += a2 * b4.w;
            acc[3][0] += a3 * b4.x; acc[3][1] += a3 * b4.y; acc[3][2] += a3 * b4.z; acc[3][3] += a3 * b4.w;
        }
    }

    #pragma unroll
    for (int i = 0; i < 4; i++)                 // STG.128 epilogue, no atomics
        *(float4*)&g_h2part[kbs][m4 + i][nb + n4] =
            make_float4(acc[i][0], acc[i][1], acc[i][2], acc[i][3]);
}

// ---------------------------------------------------------------------------
// K3: GEMM2: out += relu(sum_p h2part[p] + b2)(64x512) @ W3(512x256), K-split.
// grid = (8 n-tiles of 32, 16 k-splits of 32), block = 128 threads.
// The 8-partial summation is fused into A-staging. Also resets g_h1pre
// (its last reader, K2, precedes this kernel in stream order).
// ---------------------------------------------------------------------------
__global__ void __launch_bounds__(128) k_gemm2(
        const float* __restrict__ b2,
        const float* __restrict__ W3,
        float* __restrict__ out) {
    const int nb = blockIdx.x * 32;
    const int kb = blockIdx.y * 32;
    const int t  = threadIdx.x;
    const int m4 = (t >> 3) * 4;
    const int n4 = (t & 7) * 4;

    // Reset g_h1pre: 128 CTAs x 128 threads -> 2 elems/thread.
    {
        const int base = (blockIdx.y * gridDim.x + blockIdx.x) * 128 + t;
        g_h1pre[base] = 0.0f;
        g_h1pre[base + 16384] = 0.0f;
    }

    __shared__ float As[64][33];
    __shared__ __align__(16) float Bs[32][32];

    float acc[4][4] = {};

    #pragma unroll
    for (int i = 0; i < 4; i++) {               // As = relu(sum partials + b2)
        int idx = i * 128 + t;
        int mm = idx >> 3, k4 = (idx & 7) * 4;
        int kg = kb + k4;
        float4 s = *(const float4*)&b2[kg];
        #pragma unroll
        for (int p = 0; p < 8; p++) {
            float4 v = *(const float4*)&g_h2part[p][mm][kg];
            s.x += v.x; s.y += v.y; s.z += v.z; s.w += v.w;
        }
        As[mm][k4 + 0] = fmaxf(s.x, 0.f);
        As[mm][k4 + 1] = fmaxf(s.y, 0.f);
        As[mm][k4 + 2] = fmaxf(s.z, 0.f);
        As[mm][k4 + 3] = fmaxf(s.w, 0.f);
    }
    #pragma unroll
    for (int i = 0; i < 2; i++) {               // Bs: 32x32 of W3
        int idx = i * 128 + t;
        int k = idx >> 3, nn4 = (idx & 7) * 4;
        *(float4*)&Bs[k][nn4] =
            *(const float4*)&W3[(kb + k) * SS + nb + nn4];
    }
    __syncthreads();

    #pragma unroll
    for (int k = 0; k < 32; k++) {
        float4 b4 = *(const float4*)&Bs[k][n4];
        float a0 = As[m4 + 0][k];
        float a1 = As[m4 + 1][k];
        float a2 = As[m4 + 2][k];
        float a3 = As[m4 + 3][k];
        acc[0][0] += a0 * b4.x; acc[0][1] += a0 * b4.y; acc[0][2] += a0 * b4.z; acc[0][3] += a0 * b4.w;
        acc[1][0] += a1 * b4.x; acc[1][1] += a1 * b4.y; acc[1][2] += a1 * b4.z; acc[1][3] += a1 * b4.w;
        acc[2][0] += a2 * b4.x; acc[2][1] += a2 * b4.y; acc[2][2] += a2 * b4.z; acc[2][3] += a2 * b4.w;
        acc[3][0] += a3 * b4.x; acc[3][1] += a3 * b4.y; acc[3][2] += a3 * b4.z; acc[3][3] += a3 * b4.w;
    }

    #pragma unroll
    for (int i = 0; i < 4; i++)
        #pragma unroll
        for (int j = 0; j < 4; j++)
            atomicAdd(&out[(m4 + i) * SS + nb + n4 + j], acc[i][j]);
}

// ---------------------------------------------------------------------------
extern "C" void kernel_launch(void* const* d_in, const int* in_sizes, int n_in,
                              void* d_out, int out_size) {
    const int*   x  = (const int*)d_in[0];   // int32 or int64, detected on device
    const float* W1 = (const float*)d_in[1];
    const float* b1 = (const float*)d_in[2];
    const float* W2 = (const float*)d_in[3];
    const float* b2 = (const float*)d_in[4];
    const float* W3 = (const float*)d_in[5];
    const float* b3 = (const float*)d_in[6];
    float* out = (float*)d_out;

    k_gather<<<dim3(256, NSPLIT), 128>>>(x, W1, b3, out);
    k_gemm1<<<dim3(16, 8), 128>>>(b1, W2);
    k_gemm2<<<dim3(8, 16), 128>>>(b2, W3, out);
}